// round 2
// baseline (speedup 1.0000x reference)
#include <cuda_runtime.h>
#include <cstdint>

#define NN 100000
#define EE 1600000
#define HH 128

// ---------------- scratch (device globals; allocation-free) ----------------
__device__ float g_h[(size_t)NN * HH];
__device__ float g_tmp[(size_t)NN * HH];
__device__ float g_agg[(size_t)NN * HH];
__device__ float g_deginv[NN];
__device__ int   g_deg[NN];
__device__ int   g_cursor[NN];
__device__ int   g_rowptr[NN + 1];
__device__ int   g_csr[EE];
__device__ int   g_src32[EE];
__device__ int   g_dst32[EE];
__device__ float g_zl[NN];
__device__ float g_zr[NN];

// ---------------- CSR build ----------------
__global__ void k_init() {
    int i = blockIdx.x * blockDim.x + threadIdx.x;
    if (i < NN) { g_deg[i] = 0; g_cursor[i] = 0; }
}

// edge_index is int32 (JAX x64 disabled => jnp.int64 silently becomes int32)
__global__ void k_count(const int* __restrict__ ei) {
    int e = blockIdx.x * blockDim.x + threadIdx.x;
    if (e >= EE) return;
    int s = ei[e];
    int d = ei[EE + e];
    // defensive clamp: guarantees in-range addresses even under dtype surprise
    s = min(max(s, 0), NN - 1);
    d = min(max(d, 0), NN - 1);
    g_src32[e] = s;
    g_dst32[e] = d;
    atomicAdd(&g_deg[d], 1);
}

// single-block exclusive scan over N=100000 (1024 threads, tiled with carry)
__global__ __launch_bounds__(1024) void k_scan() {
    __shared__ int carry;
    __shared__ int wsum[32];
    int lane = threadIdx.x & 31;
    int w = threadIdx.x >> 5;
    if (threadIdx.x == 0) carry = 0;
    __syncthreads();
    for (int base = 0; base < NN; base += 1024) {
        int i = base + threadIdx.x;
        int v = (i < NN) ? g_deg[i] : 0;
        int x = v;
        #pragma unroll
        for (int d = 1; d < 32; d <<= 1) {
            int y = __shfl_up_sync(0xffffffffu, x, d);
            if (lane >= d) x += y;
        }
        if (lane == 31) wsum[w] = x;
        __syncthreads();
        if (w == 0) {
            int s = wsum[lane];
            #pragma unroll
            for (int d = 1; d < 32; d <<= 1) {
                int y = __shfl_up_sync(0xffffffffu, s, d);
                if (lane >= d) s += y;
            }
            wsum[lane] = s;
        }
        __syncthreads();
        int offset = carry + (w > 0 ? wsum[w - 1] : 0);
        int incl = offset + x;
        if (i < NN) {
            g_rowptr[i] = incl - v;  // exclusive
            g_deginv[i] = 1.0f / fmaxf((float)v, 1.0f);
        }
        __syncthreads();
        if (threadIdx.x == 1023) carry = incl;
        __syncthreads();
    }
    if (threadIdx.x == 0) g_rowptr[NN] = carry;
}

__global__ void k_fill() {
    int e = blockIdx.x * blockDim.x + threadIdx.x;
    if (e >= EE) return;
    int d = g_dst32[e];
    int p = atomicAdd(&g_cursor[d], 1);
    g_csr[g_rowptr[d] + p] = g_src32[e];
}

// ---------------- aggregation: warp per dst node ----------------
template <int F>
__global__ __launch_bounds__(256) void agg_kernel(const float* __restrict__ in,
                                                  float* __restrict__ out) {
    int warp = (blockIdx.x * blockDim.x + threadIdx.x) >> 5;
    int lane = threadIdx.x & 31;
    if (warp >= NN) return;
    int s = g_rowptr[warp], e = g_rowptr[warp + 1];
    float dinv = g_deginv[warp];
    if (F == 128) {
        float ax = 0.f, ay = 0.f, az = 0.f, aw = 0.f;
        for (int j = s; j < e; j++) {
            int src = g_csr[j];
            float4 v = __ldg((const float4*)(in + (size_t)src * 128) + lane);
            ax += v.x; ay += v.y; az += v.z; aw += v.w;
        }
        float4 o; o.x = ax * dinv; o.y = ay * dinv; o.z = az * dinv; o.w = aw * dinv;
        ((float4*)(out + (size_t)warp * 128))[lane] = o;
    } else {  // F == 64: float2 per lane
        float ax = 0.f, ay = 0.f;
        for (int j = s; j < e; j++) {
            int src = g_csr[j];
            float2 v = __ldg((const float2*)(in + (size_t)src * 64) + lane);
            ax += v.x; ay += v.y;
        }
        float2 o; o.x = ax * dinv; o.y = ay * dinv;
        ((float2*)(out + (size_t)warp * 64))[lane] = o;
    }
}

// ---------------- dual-input fp32 GEMM: C = A1@W1 (+ A2@W2) + bias, opt relu
// A: [nrows, K] row-major; W: [K, 128] row-major; C: [nrows, 128]
// 128x128 block tile, 256 threads, 8x8 per-thread tile, BK=16
__global__ __launch_bounds__(256) void gemm_dual(
    const float* __restrict__ A1, const float* __restrict__ W1,
    const float* __restrict__ A2, const float* __restrict__ W2,
    const float* __restrict__ bias, float* __restrict__ C,
    int nrows, int K, int dual, int relu)
{
    __shared__ float As[16][132];   // transposed A tile (pad for banks/alignment)
    __shared__ float Ws[16][128];

    int row0 = blockIdx.x * 128;
    int tid = threadIdx.x;
    int tr = tid >> 4;        // 0..15 -> rows tr*8..tr*8+7
    int tc = tid & 15;        // 0..15 -> cols tc*8..tc*8+7

    float acc[8][8];
    #pragma unroll
    for (int i = 0; i < 8; i++)
        #pragma unroll
        for (int j = 0; j < 8; j++) acc[i][j] = 0.f;

    int KT = dual ? 2 * K : K;
    for (int k0 = 0; k0 < KT; k0 += 16) {
        const float* A = A1;
        const float* W = W1;
        int kk = k0;
        if (k0 >= K) { A = A2; W = W2; kk = k0 - K; }

        // load A tile (128 x 16), transposed into As[k][row]
        #pragma unroll
        for (int r = 0; r < 2; r++) {
            int idx = tid + r * 256;
            int arow = idx >> 2;            // 0..127
            int ac = (idx & 3) * 4;         // 0,4,8,12
            float4 v = make_float4(0.f, 0.f, 0.f, 0.f);
            int grow = row0 + arow;
            if (grow < nrows)
                v = *(const float4*)&A[(size_t)grow * K + kk + ac];
            As[ac + 0][arow] = v.x;
            As[ac + 1][arow] = v.y;
            As[ac + 2][arow] = v.z;
            As[ac + 3][arow] = v.w;
        }
        // load W tile (16 x 128)
        #pragma unroll
        for (int r = 0; r < 2; r++) {
            int idx = tid + r * 256;
            int wrow = idx >> 5;            // 0..15
            int wc = (idx & 31) * 4;        // 0..124
            *(float4*)&Ws[wrow][wc] = *(const float4*)&W[(size_t)(kk + wrow) * 128 + wc];
        }
        __syncthreads();

        #pragma unroll
        for (int k = 0; k < 16; k++) {
            float a[8], w[8];
            *(float4*)&a[0] = *(float4*)&As[k][tr * 8];
            *(float4*)&a[4] = *(float4*)&As[k][tr * 8 + 4];
            *(float4*)&w[0] = *(float4*)&Ws[k][tc * 8];
            *(float4*)&w[4] = *(float4*)&Ws[k][tc * 8 + 4];
            #pragma unroll
            for (int i = 0; i < 8; i++)
                #pragma unroll
                for (int j = 0; j < 8; j++)
                    acc[i][j] += a[i] * w[j];
        }
        __syncthreads();
    }

    // epilogue
    float bv[8];
    *(float4*)&bv[0] = *(const float4*)&bias[tc * 8];
    *(float4*)&bv[4] = *(const float4*)&bias[tc * 8 + 4];
    #pragma unroll
    for (int i = 0; i < 8; i++) {
        int grow = row0 + tr * 8 + i;
        if (grow >= nrows) continue;
        float o[8];
        #pragma unroll
        for (int j = 0; j < 8; j++) {
            float v = acc[i][j] + bv[j];
            o[j] = relu ? fmaxf(v, 0.f) : v;
        }
        *(float4*)&C[(size_t)grow * 128 + tc * 8]     = *(float4*)&o[0];
        *(float4*)&C[(size_t)grow * 128 + tc * 8 + 4] = *(float4*)&o[4];
    }
}

// ---------------- layernorm + relu + residual-add: h += relu(LN(u)) ----------------
__global__ __launch_bounds__(256) void ln_res_kernel(const float* __restrict__ u,
                                                     const float* __restrict__ g,
                                                     const float* __restrict__ b,
                                                     float* __restrict__ h) {
    int warp = (blockIdx.x * blockDim.x + threadIdx.x) >> 5;
    int lane = threadIdx.x & 31;
    if (warp >= NN) return;
    float4 v = ((const float4*)(u + (size_t)warp * 128))[lane];
    float s = v.x + v.y + v.z + v.w;
    #pragma unroll
    for (int d = 16; d; d >>= 1) s += __shfl_xor_sync(0xffffffffu, s, d);
    float mu = s * (1.0f / 128.0f);
    float dx = v.x - mu, dy = v.y - mu, dz = v.z - mu, dw = v.w - mu;
    float q = dx * dx + dy * dy + dz * dz + dw * dw;
    #pragma unroll
    for (int d = 16; d; d >>= 1) q += __shfl_xor_sync(0xffffffffu, q, d);
    float r = rsqrtf(q * (1.0f / 128.0f) + 1e-5f);
    float4 gg = ((const float4*)g)[lane];
    float4 bb = ((const float4*)b)[lane];
    float4* hp = (float4*)(h + (size_t)warp * 128);
    float4 hv = hp[lane];
    hv.x += fmaxf(dx * r * gg.x + bb.x, 0.f);
    hv.y += fmaxf(dy * r * gg.y + bb.y, 0.f);
    hv.z += fmaxf(dz * r * gg.z + bb.z, 0.f);
    hv.w += fmaxf(dw * r * gg.w + bb.w, 0.f);
    hp[lane] = hv;
}

// ---------------- layer 4: project h to scalars (zl = h@Wl4, zr = h@Wr4) ----------------
__global__ __launch_bounds__(256) void gemv4_kernel(const float* __restrict__ h,
                                                    const float* __restrict__ wl,
                                                    const float* __restrict__ wr) {
    int warp = (blockIdx.x * blockDim.x + threadIdx.x) >> 5;
    int lane = threadIdx.x & 31;
    if (warp >= NN) return;
    float4 v = ((const float4*)(h + (size_t)warp * 128))[lane];
    float4 a = __ldg((const float4*)wl + lane);
    float4 b = __ldg((const float4*)wr + lane);
    float sl = v.x * a.x + v.y * a.y + v.z * a.z + v.w * a.w;
    float sr = v.x * b.x + v.y * b.y + v.z * b.z + v.w * b.w;
    #pragma unroll
    for (int d = 16; d; d >>= 1) {
        sl += __shfl_xor_sync(0xffffffffu, sl, d);
        sr += __shfl_xor_sync(0xffffffffu, sr, d);
    }
    if (lane == 0) { g_zl[warp] = sl; g_zr[warp] = sr; }
}

__global__ void final_kernel(const float* __restrict__ b4, float* __restrict__ out) {
    int i = blockIdx.x * blockDim.x + threadIdx.x;
    if (i >= NN) return;
    int s = g_rowptr[i], e = g_rowptr[i + 1];
    float sum = 0.f;
    for (int j = s; j < e; j++) sum += __ldg(&g_zl[g_csr[j]]);
    out[i] = g_zr[i] + b4[0] + g_deginv[i] * sum;
}

// ---------------- host ----------------
static float* symf(const void* s) {
    void* p = nullptr;
    cudaGetSymbolAddress(&p, s);
    return (float*)p;
}

extern "C" void kernel_launch(void* const* d_in, const int* in_sizes, int n_in,
                              void* d_out, int out_size) {
    const float* x    = (const float*)d_in[0];
    const int*   ei   = (const int*)d_in[1];     // int32! (JAX x64 disabled)
    const float* Wl1  = (const float*)d_in[2];
    const float* Wr1  = (const float*)d_in[3];
    const float* b1   = (const float*)d_in[4];
    const float* ln_g = (const float*)d_in[5];
    const float* ln_b = (const float*)d_in[6];
    const float* Wres = (const float*)d_in[7];
    const float* bres = (const float*)d_in[8];
    const float* Wl2  = (const float*)d_in[9];
    const float* Wr2  = (const float*)d_in[10];
    const float* b2   = (const float*)d_in[11];
    const float* Wl3  = (const float*)d_in[12];
    const float* Wr3  = (const float*)d_in[13];
    const float* b3   = (const float*)d_in[14];
    const float* Wl4  = (const float*)d_in[15];
    const float* Wr4  = (const float*)d_in[16];
    const float* b4   = (const float*)d_in[17];
    float* out = (float*)d_out;

    float* hp   = symf(g_h);
    float* tmpp = symf(g_tmp);
    float* aggp = symf(g_agg);

    const int warpBlocks = (NN + 7) / 8;          // warp-per-node kernels, 256 thr
    const int gemmBlocks = (NN + 127) / 128;      // 782
    const int edgeBlocks = (EE + 255) / 256;      // 6250
    const int nodeBlocks = (NN + 255) / 256;

    // CSR build
    k_init<<<nodeBlocks, 256>>>();
    k_count<<<edgeBlocks, 256>>>(ei);
    k_scan<<<1, 1024>>>();
    k_fill<<<edgeBlocks, 256>>>();

    // Layer 1: agg(x) -> g_agg[:, :64]
    agg_kernel<64><<<warpBlocks, 256>>>(x, aggp);
    // residual path: g_h = x @ Wres + bres
    gemm_dual<<<gemmBlocks, 256>>>(x, Wres, nullptr, nullptr, bres, hp, NN, 64, 0, 0);
    // sage1 pre-LN: g_tmp = agg @ Wl1 + x @ Wr1 + b1
    gemm_dual<<<gemmBlocks, 256>>>(aggp, Wl1, x, Wr1, b1, tmpp, NN, 64, 1, 0);
    // g_h = relu(LN(g_tmp)) + g_h
    ln_res_kernel<<<warpBlocks, 256>>>(tmpp, ln_g, ln_b, hp);

    // Layer 2: h(g_h) -> g_tmp
    agg_kernel<128><<<warpBlocks, 256>>>(hp, aggp);
    gemm_dual<<<gemmBlocks, 256>>>(aggp, Wl2, hp, Wr2, b2, tmpp, NN, 128, 1, 1);

    // Layer 3: h(g_tmp) -> g_h
    agg_kernel<128><<<warpBlocks, 256>>>(tmpp, aggp);
    gemm_dual<<<gemmBlocks, 256>>>(aggp, Wl3, tmpp, Wr3, b3, hp, NN, 128, 1, 1);

    // Layer 4: project then aggregate scalars
    gemv4_kernel<<<warpBlocks, 256>>>(hp, Wl4, Wr4);
    final_kernel<<<nodeBlocks, 256>>>(b4, out);
}

// round 4
// speedup vs baseline: 1.5985x; 1.5985x over previous
#include <cuda_runtime.h>
#include <cstdint>

#define NN 100000
#define EE 1600000
#define HH 128

// ---------------- scratch (device globals; allocation-free) ----------------
__device__ float g_h[(size_t)NN * HH];
__device__ float g_tmp[(size_t)NN * HH];
__device__ float g_agg[(size_t)NN * HH];
__device__ float g_deginv[NN];
__device__ int   g_deg[NN];
__device__ int   g_cursor[NN];
__device__ int   g_rowptr[NN + 1];
__device__ int   g_csr[EE];
__device__ int   g_src32[EE];
__device__ int   g_dst32[EE];
__device__ float g_zl[NN];
__device__ float g_zr[NN];

// ---------------- CSR build ----------------
__global__ void k_init() {
    int i = blockIdx.x * blockDim.x + threadIdx.x;
    if (i < NN) { g_deg[i] = 0; g_cursor[i] = 0; }
}

// edge_index is int32 (JAX x64 disabled => jnp.int64 silently becomes int32)
__global__ void k_count(const int* __restrict__ ei) {
    int e = blockIdx.x * blockDim.x + threadIdx.x;
    if (e >= EE) return;
    int s = ei[e];
    int d = ei[EE + e];
    s = min(max(s, 0), NN - 1);
    d = min(max(d, 0), NN - 1);
    g_src32[e] = s;
    g_dst32[e] = d;
    atomicAdd(&g_deg[d], 1);
}

__global__ __launch_bounds__(1024) void k_scan() {
    __shared__ int carry;
    __shared__ int wsum[32];
    int lane = threadIdx.x & 31;
    int w = threadIdx.x >> 5;
    if (threadIdx.x == 0) carry = 0;
    __syncthreads();
    for (int base = 0; base < NN; base += 1024) {
        int i = base + threadIdx.x;
        int v = (i < NN) ? g_deg[i] : 0;
        int x = v;
        #pragma unroll
        for (int d = 1; d < 32; d <<= 1) {
            int y = __shfl_up_sync(0xffffffffu, x, d);
            if (lane >= d) x += y;
        }
        if (lane == 31) wsum[w] = x;
        __syncthreads();
        if (w == 0) {
            int s = wsum[lane];
            #pragma unroll
            for (int d = 1; d < 32; d <<= 1) {
                int y = __shfl_up_sync(0xffffffffu, s, d);
                if (lane >= d) s += y;
            }
            wsum[lane] = s;
        }
        __syncthreads();
        int offset = carry + (w > 0 ? wsum[w - 1] : 0);
        int incl = offset + x;
        if (i < NN) {
            g_rowptr[i] = incl - v;
            g_deginv[i] = 1.0f / fmaxf((float)v, 1.0f);
        }
        __syncthreads();
        if (threadIdx.x == 1023) carry = incl;
        __syncthreads();
    }
    if (threadIdx.x == 0) g_rowptr[NN] = carry;
}

__global__ void k_fill() {
    int e = blockIdx.x * blockDim.x + threadIdx.x;
    if (e >= EE) return;
    int d = g_dst32[e];
    int p = atomicAdd(&g_cursor[d], 1);
    g_csr[g_rowptr[d] + p] = g_src32[e];
}

// ---------------- aggregation: warp per dst node ----------------
template <int F>
__global__ __launch_bounds__(256) void agg_kernel(const float* __restrict__ in,
                                                  float* __restrict__ out) {
    int warp = (blockIdx.x * blockDim.x + threadIdx.x) >> 5;
    int lane = threadIdx.x & 31;
    if (warp >= NN) return;
    int s = g_rowptr[warp], e = g_rowptr[warp + 1];
    float dinv = g_deginv[warp];
    if (F == 128) {
        float ax = 0.f, ay = 0.f, az = 0.f, aw = 0.f;
        for (int j = s; j < e; j++) {
            int src = g_csr[j];
            float4 v = __ldg((const float4*)(in + (size_t)src * 128) + lane);
            ax += v.x; ay += v.y; az += v.z; aw += v.w;
        }
        float4 o; o.x = ax * dinv; o.y = ay * dinv; o.z = az * dinv; o.w = aw * dinv;
        ((float4*)(out + (size_t)warp * 128))[lane] = o;
    } else {
        float ax = 0.f, ay = 0.f;
        for (int j = s; j < e; j++) {
            int src = g_csr[j];
            float2 v = __ldg((const float2*)(in + (size_t)src * 64) + lane);
            ax += v.x; ay += v.y;
        }
        float2 o; o.x = ax * dinv; o.y = ay * dinv;
        ((float2*)(out + (size_t)warp * 64))[lane] = o;
    }
}

// ---------------- tf32 mma.sync GEMM ----------------
// C = A1@W1 (+ A2@W2) + bias, optional relu.
// A: [NN, K] row-major, W: [K, 128] row-major, C: [NN, 128].
// Block 128x128, 8 warps (4x2), warp tile 32x64, BK=32.
__device__ __forceinline__ uint32_t f2tf32(float x) {
    uint32_t r;
    asm("cvt.rna.tf32.f32 %0, %1;" : "=r"(r) : "f"(x));
    return r;
}

#define SA_STRIDE 36
#define SB_STRIDE 132

__global__ __launch_bounds__(256, 2) void gemm_tc(
    const float* __restrict__ A1, const float* __restrict__ W1,
    const float* __restrict__ A2, const float* __restrict__ W2,
    const float* __restrict__ bias, float* __restrict__ C,
    int K, int dual, int relu)
{
    __shared__ uint32_t sA[128 * SA_STRIDE];   // A tile, row-major, tf32 bits
    __shared__ uint32_t sB[32 * SB_STRIDE];    // B tile, k-major, tf32 bits

    int tid = threadIdx.x;
    int wid = tid >> 5, lane = tid & 31;
    int g = lane >> 2, t = lane & 3;
    int row0 = blockIdx.x * 128;
    int mrow = (wid & 3) * 32;          // warp row offset in tile
    int ncol = (wid >> 2) * 64;         // warp col offset in tile

    float acc[2][8][4];
    #pragma unroll
    for (int mi = 0; mi < 2; mi++)
        #pragma unroll
        for (int nj = 0; nj < 8; nj++)
            #pragma unroll
            for (int q = 0; q < 4; q++) acc[mi][nj][q] = 0.f;

    int KT = dual ? 2 * K : K;
    for (int k0 = 0; k0 < KT; k0 += 32) {
        const float* A = A1;
        const float* W = W1;
        int kk = k0;
        if (k0 >= K) { A = A2; W = W2; kk = k0 - K; }

        // load A tile: 128 rows x 32 cols (8 float4/row)
        #pragma unroll
        for (int it = 0; it < 4; it++) {
            int idx = tid + it * 256;
            int r = idx >> 3;
            int c4 = idx & 7;
            float4 v = make_float4(0.f, 0.f, 0.f, 0.f);
            int gr = row0 + r;
            if (gr < NN) v = *(const float4*)&A[(size_t)gr * K + kk + c4 * 4];
            uint32_t* p = &sA[r * SA_STRIDE + c4 * 4];
            p[0] = f2tf32(v.x); p[1] = f2tf32(v.y);
            p[2] = f2tf32(v.z); p[3] = f2tf32(v.w);
        }
        // load B tile: 32 k-rows x 128 n-cols (32 float4/row)
        #pragma unroll
        for (int it = 0; it < 4; it++) {
            int idx = tid + it * 256;
            int kr = idx >> 5;
            int n4 = idx & 31;
            float4 v = *(const float4*)&W[(size_t)(kk + kr) * 128 + n4 * 4];
            uint32_t* p = &sB[kr * SB_STRIDE + n4 * 4];
            p[0] = f2tf32(v.x); p[1] = f2tf32(v.y);
            p[2] = f2tf32(v.z); p[3] = f2tf32(v.w);
        }
        __syncthreads();

        #pragma unroll
        for (int ks = 0; ks < 4; ks++) {
            int k = ks * 8;
            uint32_t af[2][4];
            #pragma unroll
            for (int mi = 0; mi < 2; mi++) {
                int br = mrow + mi * 16;
                af[mi][0] = sA[(br + g) * SA_STRIDE + k + t];
                af[mi][1] = sA[(br + g + 8) * SA_STRIDE + k + t];
                af[mi][2] = sA[(br + g) * SA_STRIDE + k + t + 4];
                af[mi][3] = sA[(br + g + 8) * SA_STRIDE + k + t + 4];
            }
            uint32_t bf[8][2];
            #pragma unroll
            for (int nj = 0; nj < 8; nj++) {
                int col = ncol + nj * 8 + g;
                bf[nj][0] = sB[(k + t) * SB_STRIDE + col];
                bf[nj][1] = sB[(k + t + 4) * SB_STRIDE + col];
            }
            #pragma unroll
            for (int mi = 0; mi < 2; mi++)
                #pragma unroll
                for (int nj = 0; nj < 8; nj++) {
                    asm volatile(
                        "mma.sync.aligned.m16n8k8.row.col.f32.tf32.tf32.f32 "
                        "{%0,%1,%2,%3}, {%4,%5,%6,%7}, {%8,%9}, {%0,%1,%2,%3};"
                        : "+f"(acc[mi][nj][0]), "+f"(acc[mi][nj][1]),
                          "+f"(acc[mi][nj][2]), "+f"(acc[mi][nj][3])
                        : "r"(af[mi][0]), "r"(af[mi][1]), "r"(af[mi][2]), "r"(af[mi][3]),
                          "r"(bf[nj][0]), "r"(bf[nj][1]));
                }
        }
        __syncthreads();
    }

    // epilogue
    #pragma unroll
    for (int mi = 0; mi < 2; mi++) {
        int r_lo = row0 + mrow + mi * 16 + g;
        int r_hi = r_lo + 8;
        #pragma unroll
        for (int nj = 0; nj < 8; nj++) {
            int col = ncol + nj * 8 + 2 * t;
            float b0 = bias[col], b1 = bias[col + 1];
            float2 v0, v1;
            v0.x = acc[mi][nj][0] + b0; v0.y = acc[mi][nj][1] + b1;
            v1.x = acc[mi][nj][2] + b0; v1.y = acc[mi][nj][3] + b1;
            if (relu) {
                v0.x = fmaxf(v0.x, 0.f); v0.y = fmaxf(v0.y, 0.f);
                v1.x = fmaxf(v1.x, 0.f); v1.y = fmaxf(v1.y, 0.f);
            }
            if (r_lo < NN) *(float2*)&C[(size_t)r_lo * 128 + col] = v0;
            if (r_hi < NN) *(float2*)&C[(size_t)r_hi * 128 + col] = v1;
        }
    }
}

// ---------------- layernorm + relu + residual-add: h += relu(LN(u)) ----------------
__global__ __launch_bounds__(256) void ln_res_kernel(const float* __restrict__ u,
                                                     const float* __restrict__ g,
                                                     const float* __restrict__ b,
                                                     float* __restrict__ h) {
    int warp = (blockIdx.x * blockDim.x + threadIdx.x) >> 5;
    int lane = threadIdx.x & 31;
    if (warp >= NN) return;
    float4 v = ((const float4*)(u + (size_t)warp * 128))[lane];
    float s = v.x + v.y + v.z + v.w;
    #pragma unroll
    for (int d = 16; d; d >>= 1) s += __shfl_xor_sync(0xffffffffu, s, d);
    float mu = s * (1.0f / 128.0f);
    float dx = v.x - mu, dy = v.y - mu, dz = v.z - mu, dw = v.w - mu;
    float q = dx * dx + dy * dy + dz * dz + dw * dw;
    #pragma unroll
    for (int d = 16; d; d >>= 1) q += __shfl_xor_sync(0xffffffffu, q, d);
    float r = rsqrtf(q * (1.0f / 128.0f) + 1e-5f);
    float4 gg = ((const float4*)g)[lane];
    float4 bb = ((const float4*)b)[lane];
    float4* hp = (float4*)(h + (size_t)warp * 128);
    float4 hv = hp[lane];
    hv.x += fmaxf(dx * r * gg.x + bb.x, 0.f);
    hv.y += fmaxf(dy * r * gg.y + bb.y, 0.f);
    hv.z += fmaxf(dz * r * gg.z + bb.z, 0.f);
    hv.w += fmaxf(dw * r * gg.w + bb.w, 0.f);
    hp[lane] = hv;
}

// ---------------- layer 4: project h to scalars ----------------
__global__ __launch_bounds__(256) void gemv4_kernel(const float* __restrict__ h,
                                                    const float* __restrict__ wl,
                                                    const float* __restrict__ wr) {
    int warp = (blockIdx.x * blockDim.x + threadIdx.x) >> 5;
    int lane = threadIdx.x & 31;
    if (warp >= NN) return;
    float4 v = ((const float4*)(h + (size_t)warp * 128))[lane];
    float4 a = __ldg((const float4*)wl + lane);
    float4 b = __ldg((const float4*)wr + lane);
    float sl = v.x * a.x + v.y * a.y + v.z * a.z + v.w * a.w;
    float sr = v.x * b.x + v.y * b.y + v.z * b.z + v.w * b.w;
    #pragma unroll
    for (int d = 16; d; d >>= 1) {
        sl += __shfl_xor_sync(0xffffffffu, sl, d);
        sr += __shfl_xor_sync(0xffffffffu, sr, d);
    }
    if (lane == 0) { g_zl[warp] = sl; g_zr[warp] = sr; }
}

__global__ void final_kernel(const float* __restrict__ b4, float* __restrict__ out) {
    int i = blockIdx.x * blockDim.x + threadIdx.x;
    if (i >= NN) return;
    int s = g_rowptr[i], e = g_rowptr[i + 1];
    float sum = 0.f;
    for (int j = s; j < e; j++) sum += __ldg(&g_zl[g_csr[j]]);
    out[i] = g_zr[i] + b4[0] + g_deginv[i] * sum;
}

// ---------------- host ----------------
static float* symf(const void* s) {
    void* p = nullptr;
    cudaGetSymbolAddress(&p, s);
    return (float*)p;
}

extern "C" void kernel_launch(void* const* d_in, const int* in_sizes, int n_in,
                              void* d_out, int out_size) {
    const float* x    = (const float*)d_in[0];
    const int*   ei   = (const int*)d_in[1];     // int32 (JAX x64 disabled)
    const float* Wl1  = (const float*)d_in[2];
    const float* Wr1  = (const float*)d_in[3];
    const float* b1   = (const float*)d_in[4];
    const float* ln_g = (const float*)d_in[5];
    const float* ln_b = (const float*)d_in[6];
    const float* Wres = (const float*)d_in[7];
    const float* bres = (const float*)d_in[8];
    const float* Wl2  = (const float*)d_in[9];
    const float* Wr2  = (const float*)d_in[10];
    const float* b2   = (const float*)d_in[11];
    const float* Wl3  = (const float*)d_in[12];
    const float* Wr3  = (const float*)d_in[13];
    const float* b3   = (const float*)d_in[14];
    const float* Wl4  = (const float*)d_in[15];
    const float* Wr4  = (const float*)d_in[16];
    const float* b4   = (const float*)d_in[17];
    float* out = (float*)d_out;

    float* hp   = symf(g_h);
    float* tmpp = symf(g_tmp);
    float* aggp = symf(g_agg);

    const int warpBlocks = (NN + 7) / 8;
    const int gemmBlocks = (NN + 127) / 128;      // 782
    const int edgeBlocks = (EE + 255) / 256;
    const int nodeBlocks = (NN + 255) / 256;

    // CSR build
    k_init<<<nodeBlocks, 256>>>();
    k_count<<<edgeBlocks, 256>>>(ei);
    k_scan<<<1, 1024>>>();
    k_fill<<<edgeBlocks, 256>>>();

    // Layer 1
    agg_kernel<64><<<warpBlocks, 256>>>(x, aggp);
    // residual: h = x @ Wres + bres
    gemm_tc<<<gemmBlocks, 256>>>(x, Wres, nullptr, nullptr, bres, hp, 64, 0, 0);
    // tmp = agg @ Wl1 + x @ Wr1 + b1
    gemm_tc<<<gemmBlocks, 256>>>(aggp, Wl1, x, Wr1, b1, tmpp, 64, 1, 0);
    // h += relu(LN(tmp))
    ln_res_kernel<<<warpBlocks, 256>>>(tmpp, ln_g, ln_b, hp);

    // Layer 2: tmp = relu(agg(h) @ Wl2 + h @ Wr2 + b2)
    agg_kernel<128><<<warpBlocks, 256>>>(hp, aggp);
    gemm_tc<<<gemmBlocks, 256>>>(aggp, Wl2, hp, Wr2, b2, tmpp, 128, 1, 1);

    // Layer 3: h = relu(agg(tmp) @ Wl3 + tmp @ Wr3 + b3)
    agg_kernel<128><<<warpBlocks, 256>>>(tmpp, aggp);
    gemm_tc<<<gemmBlocks, 256>>>(aggp, Wl3, tmpp, Wr3, b3, hp, 128, 1, 1);

    // Layer 4
    gemv4_kernel<<<warpBlocks, 256>>>(hp, Wl4, Wr4);
    final_kernel<<<nodeBlocks, 256>>>(b4, out);
}